// round 9
// baseline (speedup 1.0000x reference)
#include <cuda_runtime.h>
#include <cooperative_groups.h>
#include <math.h>

namespace cg = cooperative_groups;

#define TT 196            // tokens
#define CC 640            // channels
#define CLN 10            // cluster: 5 channel-chunks x 2 tensors
#define GRP 5             // chunks per tensor
#define CHUNK 128         // channels per CTA
#define TPB 512
#define NW 16
#define CSPL 2            // channel splits in column passes
#define CSPC (CHUNK/CSPL) // 64 channels per split
#define TILE_ELEMS (CHUNK * TT)        // 25088
#define TILE_BYTES (TILE_ELEMS * 4)    // 100352
#define NTC 4                          // TMA sub-chunks
#define TCH_CH (CHUNK / NTC)           // 32 channels per TMA chunk
#define TCH_BYTES (TCH_CH * TT * 4)    // 25088 bytes

__device__ __forceinline__ float warp_sum(float v) {
#pragma unroll
    for (int o = 16; o; o >>= 1) v += __shfl_xor_sync(0xffffffffu, v, o);
    return v;
}
__device__ __forceinline__ float warp_max(float v) {
#pragma unroll
    for (int o = 16; o; o >>= 1) v = fmaxf(v, __shfl_xor_sync(0xffffffffu, v, o));
    return v;
}

__device__ __forceinline__ unsigned su32(const void* p) {
    unsigned a;
    asm("{ .reg .u64 t; cvta.to.shared.u64 t, %1; cvt.u32.u64 %0, t; }"
        : "=r"(a) : "l"(p));
    return a;
}
__device__ __forceinline__ void mbar_init(unsigned mb, unsigned cnt) {
    asm volatile("mbarrier.init.shared.b64 [%0], %1;" :: "r"(mb), "r"(cnt) : "memory");
}
__device__ __forceinline__ void mbar_expect_tx(unsigned mb, unsigned bytes) {
    asm volatile("mbarrier.arrive.expect_tx.shared.b64 _, [%0], %1;"
                 :: "r"(mb), "r"(bytes) : "memory");
}
// plain wait (acquire.cta) — used for TMA completion
__device__ __forceinline__ void mbar_wait(unsigned mb, unsigned parity) {
    asm volatile(
        "{\n\t.reg .pred p;\n\t"
        "WL_%=:\n\t"
        "mbarrier.try_wait.parity.shared.b64 p, [%0], %1;\n\t"
        "@!p bra WL_%=;\n\t}"
        :: "r"(mb), "r"(parity) : "memory");
}
// acquire.cluster wait — consumer side of cross-CTA handoffs
__device__ __forceinline__ void mbar_wait_acq(unsigned mb, unsigned parity) {
    asm volatile(
        "{\n\t.reg .pred p;\n\t"
        "WA_%=:\n\t"
        "mbarrier.try_wait.parity.acquire.cluster.shared::cta.b64 p, [%0], %1;\n\t"
        "@!p bra WA_%=;\n\t}"
        :: "r"(mb), "r"(parity) : "memory");
}
// release.cluster arrive on the same-offset mbarrier in CTA `target`
__device__ __forceinline__ void mbar_arrive_remote(unsigned local_mb, unsigned target) {
    asm volatile(
        "{\n\t.reg .b32 r;\n\t"
        "mapa.shared::cluster.u32 r, %0, %1;\n\t"
        "mbarrier.arrive.release.cluster.shared::cluster.b64 _, [r];\n\t}"
        :: "r"(local_mb), "r"(target) : "memory");
}
__device__ __forceinline__ void mbar_arrive_local(unsigned mb) {
    asm volatile("mbarrier.arrive.shared.b64 _, [%0];" :: "r"(mb) : "memory");
}
__device__ __forceinline__ void bulk_g2s(unsigned dst, const void* src,
                                         unsigned bytes, unsigned mb) {
    asm volatile(
        "cp.async.bulk.shared::cta.global.mbarrier::complete_tx::bytes "
        "[%0], [%1], %2, [%3];"
        :: "r"(dst), "l"(src), "r"(bytes), "r"(mb) : "memory");
}
__device__ __forceinline__ void cluster_arrive_() {
    asm volatile("barrier.cluster.arrive.aligned;" ::: "memory");
}
__device__ __forceinline__ void cluster_wait_() {
    asm volatile("barrier.cluster.wait.aligned;" ::: "memory");
}

struct State {
    // part[0] is the remote-readable partial for each column pass; each pass
    // has its own ready-mbarrier, so reuse across passes is safe.
    alignas(16) float part[CSPL][TT];
    alignas(16) float a4[TT];     // 1 + attn (float4-readable)
    float invn[TT];               // 1/||token||
    float m[TT];                  // m, then logits
    float kw[TT];                 // k * invn
    float bar[CHUNK];             // my bar chunk   (remote-read by peer)
    float v[CHUNK];               // my v chunk     (remote-read by peer)
    float obar[CHUNK];            // local copy of peer bar / peer v
    float h[32];                  // MLP hidden
    float red[2];                 // softmax reduce
    // mbars: [0..3] TMA chunks, 4=A(sumsq), 5=M, 6=L, 7=bar-pair, 8=v-pair
    alignas(8) unsigned long long mbars[9];
};

__global__ void __launch_bounds__(TPB, 2)
cross_attn_p2p(const float* __restrict__ cls_all, const float* __restrict__ qry_all,
               const float* __restrict__ cw1, const float* __restrict__ cb1,
               const float* __restrict__ cw2, const float* __restrict__ cb2,
               const float* __restrict__ qw1, const float* __restrict__ qb1,
               const float* __restrict__ qw2, const float* __restrict__ qb2,
               float* __restrict__ oc_all, float* __restrict__ oq_all) {
    extern __shared__ float tile[];   // [CHUNK][TT]
    __shared__ State s;

    cg::cluster_group cl = cg::this_cluster();
    const int tid  = threadIdx.x;
    const int lane = tid & 31;
    const int wid  = tid >> 5;
    const unsigned rank  = cl.block_rank();           // 0..9
    const bool isClass   = rank < GRP;
    const unsigned chunk = isClass ? rank : rank - GRP;
    const unsigned gbase = isClass ? 0u : (unsigned)GRP;
    const unsigned peer  = isClass ? rank + GRP : rank - GRP;
    const int batch = blockIdx.x / CLN;

    const size_t off = (size_t)batch * CC * TT + (size_t)chunk * CHUNK * TT;
    const float* X = (isClass ? cls_all : qry_all) + off;
    float*       O = (isClass ? oc_all  : oq_all ) + off;

    // Class CTAs compute m_q -> run the QUERY-side MLP, and vice versa.
    const float* w1 = isClass ? qw1 : cw1;
    const float* b1 = isClass ? qb1 : cb1;
    const float* w2 = isClass ? qw2 : cw2;
    const float* b2 = isClass ? qb2 : cb2;

    const int ct = tid % TT;          // token (column passes)
    const int cs = tid / TT;          // split (0,1; >=2 idle)

    const unsigned tileA = su32(tile);
    const unsigned mb0   = su32(&s.mbars[0]);
    const unsigned mbA   = mb0 + 4 * 8;
    const unsigned mbM   = mb0 + 5 * 8;
    const unsigned mbL   = mb0 + 6 * 8;
    const unsigned mbBar = mb0 + 7 * 8;
    const unsigned mbV   = mb0 + 8 * 8;

    // ---- init mbarriers, kick chunked TMA ----------------------------------
    if (tid == 0) {
#pragma unroll
        for (int j = 0; j < NTC; ++j) mbar_init(mb0 + j * 8, 1);
        mbar_init(mbA, GRP); mbar_init(mbM, GRP); mbar_init(mbL, GRP);
        mbar_init(mbBar, 1); mbar_init(mbV, 1);
    }
    __syncthreads();
    if (tid == 0) {
#pragma unroll
        for (int j = 0; j < NTC; ++j) {
            mbar_expect_tx(mb0 + j * 8, TCH_BYTES);
            bulk_g2s(tileA + j * TCH_BYTES,
                     X + (size_t)j * TCH_CH * TT, TCH_BYTES, mb0 + j * 8);
        }
    }
    // all CTAs' mbarriers must be initialized before any remote arrive
    cluster_arrive_(); cluster_wait_();

    // ---- Phase 1: sumsq partial, overlapped with TMA arrival ---------------
    if (cs < CSPL) {
        const float* p = tile + cs * CSPC * TT + ct;
        float acc = 0.f;
        mbar_wait(mb0 + (2 * cs) * 8, 0);
#pragma unroll 8
        for (int c = 0; c < TCH_CH; ++c) {
            float v = p[c * TT];
            acc = fmaf(v, v, acc);
        }
        mbar_wait(mb0 + (2 * cs + 1) * 8, 0);
#pragma unroll 8
        for (int c = TCH_CH; c < CSPC; ++c) {
            float v = p[c * TT];
            acc = fmaf(v, v, acc);
        }
        s.part[cs][ct] = acc;
    }
    __syncthreads();
    if (tid < TT) s.part[0][tid] += s.part[1][tid];
    __syncthreads();
    if (tid == 0) {
        mbar_arrive_local(mbA);
#pragma unroll
        for (unsigned i = 0; i < GRP; ++i)
            if (gbase + i != rank) mbar_arrive_remote(mbA, gbase + i);
    }

    // ---- invn (group reduce over 5 ranks) + bar (local row reduce) ---------
    if (tid < TT) {
        mbar_wait_acq(mbA, 0);
        float ss = 0.f;
#pragma unroll
        for (unsigned i = 0; i < GRP; ++i)
            ss += cl.map_shared_rank(&s.part[0][0], gbase + i)[tid];
        s.invn[tid] = 1.f / fmaxf(sqrtf(ss), 1e-12f);
    }
    __syncthreads();
    for (int c = wid; c < CHUNK; c += NW) {
        float acc = 0.f;
        for (int t = lane; t < TT; t += 32)
            acc = fmaf(tile[c * TT + t], s.invn[t], acc);
        acc = warp_sum(acc);
        if (lane == 0) s.bar[c] = acc * (1.f / (float)TT);
    }
    __syncthreads();
    if (tid == 0) mbar_arrive_remote(mbBar, peer);   // my bar is ready for peer

    // ---- m partial: sum_c peer_bar[c] * tile[c][t] -------------------------
    if (tid < CHUNK) {
        mbar_wait_acq(mbBar, 0);
        s.obar[tid] = cl.map_shared_rank(s.bar, peer)[tid];
    }
    __syncthreads();
    if (cs < CSPL) {
        const float* p = tile + cs * CSPC * TT + ct;
        const float* wv = s.obar + cs * CSPC;
        float acc = 0.f;
#pragma unroll 8
        for (int c = 0; c < CSPC; ++c)
            acc = fmaf(wv[c], p[c * TT], acc);
        s.part[cs][ct] = acc;
    }
    __syncthreads();
    if (tid < TT) s.part[0][tid] += s.part[1][tid];
    __syncthreads();
    if (tid == 0) {
        mbar_arrive_local(mbM);
#pragma unroll
        for (unsigned i = 0; i < GRP; ++i)
            if (gbase + i != rank) mbar_arrive_remote(mbM, gbase + i);
    }

    // ---- m reduce, tiny MLP -> kw = k * invn, then v (local row reduce) ----
    if (tid < TT) {
        mbar_wait_acq(mbM, 0);
        float mm = 0.f;
#pragma unroll
        for (unsigned i = 0; i < GRP; ++i)
            mm += cl.map_shared_rank(&s.part[0][0], gbase + i)[tid];
        s.m[tid] = mm * s.invn[tid];
    }
    __syncthreads();
    {   // hidden: 512 thr = 32 hidden units x 16 split-K
        const int hh = tid >> 4;
        const int tg = tid & 15;
        float acc = 0.f;
        for (int t = tg; t < TT; t += 16)
            acc = fmaf(s.m[t], w1[t * 32 + hh], acc);
#pragma unroll
        for (int o = 8; o; o >>= 1) acc += __shfl_xor_sync(0xffffffffu, acc, o);
        if (tg == 0) s.h[hh] = fmaxf(acc + b1[hh], 0.f);
    }
    __syncthreads();
    if (tid < TT) {
        float acc = b2[tid];
#pragma unroll
        for (int hh = 0; hh < 32; ++hh)
            acc = fmaf(s.h[hh], w2[hh * TT + tid], acc);
        s.kw[tid] = acc * s.invn[tid];
    }
    __syncthreads();
    for (int c = wid; c < CHUNK; c += NW) {
        float acc = 0.f;
        for (int t = lane; t < TT; t += 32)
            acc = fmaf(tile[c * TT + t], s.kw[t], acc);
        acc = warp_sum(acc);
        if (lane == 0) s.v[c] = acc;
    }
    __syncthreads();
    if (tid == 0) mbar_arrive_remote(mbV, peer);     // my v is ready for peer

    // ---- logit partial: sum_c peer_v[c] * tile[c][t] -----------------------
    if (tid < CHUNK) {
        mbar_wait_acq(mbV, 0);
        s.obar[tid] = cl.map_shared_rank(s.v, peer)[tid];
    }
    __syncthreads();
    if (cs < CSPL) {
        const float* p = tile + cs * CSPC * TT + ct;
        const float* wv = s.obar + cs * CSPC;
        float acc = 0.f;
#pragma unroll 8
        for (int c = 0; c < CSPC; ++c)
            acc = fmaf(wv[c], p[c * TT], acc);
        s.part[cs][ct] = acc;
    }
    __syncthreads();
    if (tid < TT) s.part[0][tid] += s.part[1][tid];
    __syncthreads();
    if (tid == 0) {
        mbar_arrive_local(mbL);
#pragma unroll
        for (unsigned i = 0; i < GRP; ++i)
            if (gbase + i != rank) mbar_arrive_remote(mbL, gbase + i);
    }

    // ---- logits reduce (last remote reads), softmax ------------------------
    if (tid < TT) {
        mbar_wait_acq(mbL, 0);
        float ll = 0.f;
#pragma unroll
        for (unsigned i = 0; i < GRP; ++i)
            ll += cl.map_shared_rank(&s.part[0][0], gbase + i)[tid];
        s.m[tid] = ll * s.invn[tid] * 40.f;   // /0.025
    }
    __syncthreads();
    cluster_arrive_();   // past all my remote reads; wait() at kernel end

    if (wid == 0) {
        float v = -3.4e38f;
        for (int t = lane; t < TT; t += 32) v = fmaxf(v, s.m[t]);
        v = warp_max(v);
        if (lane == 0) s.red[0] = v;
    }
    __syncthreads();
    if (tid < TT) s.m[tid] = __expf(s.m[tid] - s.red[0]);
    __syncthreads();
    if (wid == 0) {
        float v = 0.f;
        for (int t = lane; t < TT; t += 32) v += s.m[t];
        v = warp_sum(v);
        if (lane == 0) s.red[1] = 1.f / v;
    }
    __syncthreads();
    if (tid < TT) s.a4[tid] = 1.f + s.m[tid] * s.red[1];
    __syncthreads();

    // ---- output: out = tile * (1 + attn[token]) ----------------------------
    {
        const float4* t4 = reinterpret_cast<const float4*>(tile);
        const float4* a4 = reinterpret_cast<const float4*>(s.a4);
        float4* o4 = reinterpret_cast<float4*>(O);
        const int N4 = TILE_ELEMS / 4;   // 6272; channel row = 49 float4
        for (int i = tid; i < N4; i += TPB) {
            float4 v = t4[i];
            float4 a = a4[i % 49];
            v.x *= a.x; v.y *= a.y; v.z *= a.z; v.w *= a.w;
            o4[i] = v;
        }
    }

    cluster_wait_();  // keep SMEM alive until all peers are past their remote reads
}

extern "C" void kernel_launch(void* const* d_in, const int* in_sizes, int n_in,
                              void* d_out, int out_size) {
    const float* cls = (const float*)d_in[0];
    const float* qry = (const float*)d_in[1];
    const float* cw1 = (const float*)d_in[2];
    const float* cb1 = (const float*)d_in[3];
    const float* cw2 = (const float*)d_in[4];
    const float* cb2 = (const float*)d_in[5];
    const float* qw1 = (const float*)d_in[6];
    const float* qb1 = (const float*)d_in[7];
    const float* qw2 = (const float*)d_in[8];
    const float* qb2 = (const float*)d_in[9];

    const int B = in_sizes[0] / (CC * TT);  // 512
    float* oc = (float*)d_out;
    float* oq = oc + (size_t)B * CC * TT;

    cudaFuncSetAttribute(cross_attn_p2p,
                         cudaFuncAttributeMaxDynamicSharedMemorySize, TILE_BYTES);
    cudaFuncSetAttribute(cross_attn_p2p,
                         cudaFuncAttributeNonPortableClusterSizeAllowed, 1);

    cudaLaunchConfig_t cfg = {};
    cfg.gridDim  = dim3(B * CLN, 1, 1);
    cfg.blockDim = dim3(TPB, 1, 1);
    cfg.dynamicSmemBytes = TILE_BYTES;
    cudaLaunchAttribute attrs[1];
    attrs[0].id = cudaLaunchAttributeClusterDimension;
    attrs[0].val.clusterDim = {CLN, 1, 1};
    cfg.attrs = attrs;
    cfg.numAttrs = 1;

    cudaLaunchKernelEx(&cfg, cross_attn_p2p,
                       cls, qry, cw1, cb1, cw2, cb2, qw1, qb1, qw2, qb2, oc, oq);
}

// round 10
// speedup vs baseline: 1.6758x; 1.6758x over previous
#include <cuda_runtime.h>
#include <cuda_bf16.h>
#include <cooperative_groups.h>
#include <math.h>

namespace cg = cooperative_groups;

#define TT 196            // tokens
#define TQ 49             // token quads
#define CC 640            // channels
#define CLN 10            // cluster: 5 channel-chunks x 2 tensors
#define GRP 5             // chunks per tensor
#define CHUNK 128         // channels per CTA
#define TPB 256
#define NW 8
#define TILE_ELEMS (CHUNK * TT)             // 25088
#define TILE_BYTES (TILE_ELEMS * 2)         // 50176 (bf16)
#define MAXB 512

// (1 + attn) multipliers: [batch][side(0=class,1=query)][token]
__device__ float g_mult[MAXB * 2 * TT];

__device__ __forceinline__ float warp_sum(float v) {
#pragma unroll
    for (int o = 16; o; o >>= 1) v += __shfl_xor_sync(0xffffffffu, v, o);
    return v;
}
__device__ __forceinline__ float warp_max(float v) {
#pragma unroll
    for (int o = 16; o; o >>= 1) v = fmaxf(v, __shfl_xor_sync(0xffffffffu, v, o));
    return v;
}
__device__ __forceinline__ void cluster_arrive_() {
    asm volatile("barrier.cluster.arrive.aligned;" ::: "memory");
}
__device__ __forceinline__ void cluster_wait_() {
    asm volatile("barrier.cluster.wait.aligned;" ::: "memory");
}

struct StateA {
    alignas(16) float part[TT];   // column-pass partial (remote-read by group)
    alignas(16) float invn[TT];   // 1/||token||
    alignas(16) float m[TT];      // m, then logits, then 1+attn
    alignas(16) float kw[TT];     // k * invn
    float bar[CHUNK];             // my bar chunk (remote-read by peer)
    float v[CHUNK];               // my v chunk   (remote-read by peer)
    float obar[CHUNK];            // local copy of peer bar / v
    float h[32];                  // MLP hidden
    float red[2];                 // softmax reduce
};

// ============================ Kernel A =====================================
// Computes the per-batch attention multipliers only. bf16 tile, fp32 math.
__global__ void __launch_bounds__(TPB, 4)
attn_weights_kernel(const float* __restrict__ cls_all, const float* __restrict__ qry_all,
                    const float* __restrict__ cw1, const float* __restrict__ cb1,
                    const float* __restrict__ cw2, const float* __restrict__ cb2,
                    const float* __restrict__ qw1, const float* __restrict__ qb1,
                    const float* __restrict__ qw2, const float* __restrict__ qb2) {
    extern __shared__ __nv_bfloat16 tile[];   // [CHUNK][TT] bf16
    __shared__ StateA s;

    cg::cluster_group cl = cg::this_cluster();
    const int tid  = threadIdx.x;
    const int lane = tid & 31;
    const int wid  = tid >> 5;
    const unsigned rank  = cl.block_rank();           // 0..9
    const bool isClass   = rank < GRP;
    const unsigned chunk = isClass ? rank : rank - GRP;
    const unsigned gbase = isClass ? 0u : (unsigned)GRP;
    const unsigned peer  = isClass ? rank + GRP : rank - GRP;
    const int batch = blockIdx.x / CLN;

    const size_t off = (size_t)batch * CC * TT + (size_t)chunk * CHUNK * TT;
    const float* X = (isClass ? cls_all : qry_all) + off;

    // Class CTAs run the QUERY-side MLP (their m partial is m_q) and v-pass
    // produces v_q for the peer; symmetric for query CTAs. (Verified R2-R8.)
    const float* w1 = isClass ? qw1 : cw1;
    const float* b1 = isClass ? qb1 : cb1;
    const float* w2 = isClass ? qw2 : cw2;
    const float* b2 = isClass ? qb2 : cb2;

    // ---- load: global fp32 -> bf16 tile ------------------------------------
    {
        const float4* g4 = reinterpret_cast<const float4*>(X);
        uint4* t16 = reinterpret_cast<uint4*>(tile);
        const int NU = TILE_ELEMS / 8;  // 3136 uint4 (8 bf16 each)
        for (int i = tid; i < NU; i += TPB) {
            float4 a = g4[2 * i];
            float4 b = g4[2 * i + 1];
            __nv_bfloat162 p0 = __floats2bfloat162_rn(a.x, a.y);
            __nv_bfloat162 p1 = __floats2bfloat162_rn(a.z, a.w);
            __nv_bfloat162 p2 = __floats2bfloat162_rn(b.x, b.y);
            __nv_bfloat162 p3 = __floats2bfloat162_rn(b.z, b.w);
            uint4 u;
            u.x = *reinterpret_cast<unsigned*>(&p0);
            u.y = *reinterpret_cast<unsigned*>(&p1);
            u.z = *reinterpret_cast<unsigned*>(&p2);
            u.w = *reinterpret_cast<unsigned*>(&p3);
            t16[i] = u;
        }
    }
    __syncthreads();

    // ---- Phase 1: sumsq partial over my channels ---------------------------
    if (tid < TT) {
        float acc = 0.f;
#pragma unroll 8
        for (int c = 0; c < CHUNK; ++c) {
            float v = __bfloat162float(tile[c * TT + tid]);
            acc = fmaf(v, v, acc);
        }
        s.part[tid] = acc;
    }
    cl.sync();  // S1

    // ---- invn (group reduce) + bar (local row reduce) ----------------------
    if (tid < TT) {
        float ss = 0.f;
#pragma unroll
        for (unsigned i = 0; i < GRP; ++i)
            ss += cl.map_shared_rank(s.part, gbase + i)[tid];
        s.invn[tid] = 1.f / fmaxf(sqrtf(ss), 1e-12f);
    }
    __syncthreads();
    for (int c = wid; c < CHUNK; c += NW) {
        const __nv_bfloat162* row = reinterpret_cast<const __nv_bfloat162*>(tile + c * TT);
        float acc = 0.f;
        for (int i = lane; i < TT / 2; i += 32) {
            float2 x = __bfloat1622float2(row[i]);
            acc = fmaf(x.x, s.invn[2 * i], acc);
            acc = fmaf(x.y, s.invn[2 * i + 1], acc);
        }
        acc = warp_sum(acc);
        if (lane == 0) s.bar[c] = acc * (1.f / (float)TT);
    }
    cl.sync();  // S2

    // ---- m partial: sum_c peer_bar[c] * tile[c][t] -------------------------
    if (tid < CHUNK) s.obar[tid] = cl.map_shared_rank(s.bar, peer)[tid];
    __syncthreads();
    if (tid < TT) {
        float acc = 0.f;
#pragma unroll 8
        for (int c = 0; c < CHUNK; ++c)
            acc = fmaf(s.obar[c], __bfloat162float(tile[c * TT + tid]), acc);
        s.part[tid] = acc;
    }
    cl.sync();  // S3

    // ---- m reduce, MLP -> kw, v row pass -----------------------------------
    if (tid < TT) {
        float mm = 0.f;
#pragma unroll
        for (unsigned i = 0; i < GRP; ++i)
            mm += cl.map_shared_rank(s.part, gbase + i)[tid];
        s.m[tid] = mm * s.invn[tid];
    }
    __syncthreads();
    {   // hidden: 256 thr = 32 units x 8 split-K
        const int hh = tid >> 3;
        const int tg = tid & 7;
        float acc = 0.f;
        for (int t = tg; t < TT; t += 8)
            acc = fmaf(s.m[t], w1[t * 32 + hh], acc);
#pragma unroll
        for (int o = 4; o; o >>= 1) acc += __shfl_xor_sync(0xffffffffu, acc, o);
        if (tg == 0) s.h[hh] = fmaxf(acc + b1[hh], 0.f);
    }
    __syncthreads();
    if (tid < TT) {
        float acc = b2[tid];
#pragma unroll
        for (int hh = 0; hh < 32; ++hh)
            acc = fmaf(s.h[hh], w2[hh * TT + tid], acc);
        s.kw[tid] = acc * s.invn[tid];
    }
    __syncthreads();
    for (int c = wid; c < CHUNK; c += NW) {
        const __nv_bfloat162* row = reinterpret_cast<const __nv_bfloat162*>(tile + c * TT);
        float acc = 0.f;
        for (int i = lane; i < TT / 2; i += 32) {
            float2 x = __bfloat1622float2(row[i]);
            acc = fmaf(x.x, s.kw[2 * i], acc);
            acc = fmaf(x.y, s.kw[2 * i + 1], acc);
        }
        acc = warp_sum(acc);
        if (lane == 0) s.v[c] = acc;
    }
    cl.sync();  // S4

    // ---- logit partial: sum_c peer_v[c] * tile[c][t] -----------------------
    if (tid < CHUNK) s.obar[tid] = cl.map_shared_rank(s.v, peer)[tid];
    __syncthreads();
    if (tid < TT) {
        float acc = 0.f;
#pragma unroll 8
        for (int c = 0; c < CHUNK; ++c)
            acc = fmaf(s.obar[c], __bfloat162float(tile[c * TT + tid]), acc);
        s.part[tid] = acc;
    }
    cl.sync();  // S5

    // ---- logits reduce (last remote reads), softmax, store -----------------
    if (tid < TT) {
        float ll = 0.f;
#pragma unroll
        for (unsigned i = 0; i < GRP; ++i)
            ll += cl.map_shared_rank(s.part, gbase + i)[tid];
        s.m[tid] = ll * s.invn[tid] * 40.f;   // /0.025
    }
    __syncthreads();
    cluster_arrive_();   // past all my remote reads; wait at end

    if (wid == 0) {
        float v = -3.4e38f;
        for (int t = lane; t < TT; t += 32) v = fmaxf(v, s.m[t]);
        v = warp_max(v);
        if (lane == 0) s.red[0] = v;
    }
    __syncthreads();
    if (tid < TT) s.m[tid] = __expf(s.m[tid] - s.red[0]);
    __syncthreads();
    if (wid == 0) {
        float v = 0.f;
        for (int t = lane; t < TT; t += 32) v += s.m[t];
        v = warp_sum(v);
        if (lane == 0) s.red[1] = 1.f / v;
    }
    __syncthreads();
    // class attn lives on class CTAs; query attn on query CTAs. chunk 0 writes.
    if (chunk == 0 && tid < TT) {
        float mult = 1.f + s.m[tid] * s.red[1];
        g_mult[(batch * 2 + (isClass ? 0 : 1)) * TT + tid] = mult;
    }

    cluster_wait_();  // keep SMEM alive until peers finished remote reads
}

// ============================ Kernel B =====================================
// Streaming epilogue: out = feat * mult[b, side, token]. Pure bandwidth.
#define BTPB 256
#define NSL 4             // channel slices per (batch, side)
#define SLCH (CC / NSL)   // 160 channels per slice

__global__ void __launch_bounds__(BTPB)
apply_kernel(const float* __restrict__ cls_all, const float* __restrict__ qry_all,
             float* __restrict__ oc_all, float* __restrict__ oq_all) {
    __shared__ float mult[TT];
    const int b    = blockIdx.y;
    const int sx   = blockIdx.x;        // 0..2*NSL-1
    const int side = sx >= NSL;         // 0=class, 1=query
    const int sl   = side ? sx - NSL : sx;
    const int tid  = threadIdx.x;

    if (tid < TT) mult[tid] = g_mult[(b * 2 + side) * TT + tid];
    __syncthreads();

    const size_t off = (size_t)b * CC * TT + (size_t)sl * SLCH * TT;
    const float4* in4 = reinterpret_cast<const float4*>((side ? qry_all : cls_all) + off);
    float4* out4 = reinterpret_cast<float4*>((side ? oq_all : oc_all) + off);

    const int N4 = SLCH * TT / 4;   // 7840 float4; channel row = 49 quads
    const float4* m4 = reinterpret_cast<const float4*>(mult);
#pragma unroll 4
    for (int i = tid; i < N4; i += BTPB) {
        float4 v = in4[i];
        float4 a = m4[i % TQ];
        v.x *= a.x; v.y *= a.y; v.z *= a.z; v.w *= a.w;
        out4[i] = v;
    }
}

extern "C" void kernel_launch(void* const* d_in, const int* in_sizes, int n_in,
                              void* d_out, int out_size) {
    const float* cls = (const float*)d_in[0];
    const float* qry = (const float*)d_in[1];
    const float* cw1 = (const float*)d_in[2];
    const float* cb1 = (const float*)d_in[3];
    const float* cw2 = (const float*)d_in[4];
    const float* cb2 = (const float*)d_in[5];
    const float* qw1 = (const float*)d_in[6];
    const float* qb1 = (const float*)d_in[7];
    const float* qw2 = (const float*)d_in[8];
    const float* qb2 = (const float*)d_in[9];

    const int B = in_sizes[0] / (CC * TT);  // 512
    float* oc = (float*)d_out;
    float* oq = oc + (size_t)B * CC * TT;

    cudaFuncSetAttribute(attn_weights_kernel,
                         cudaFuncAttributeMaxDynamicSharedMemorySize, TILE_BYTES);
    cudaFuncSetAttribute(attn_weights_kernel,
                         cudaFuncAttributeNonPortableClusterSizeAllowed, 1);

    cudaLaunchConfig_t cfg = {};
    cfg.gridDim  = dim3(B * CLN, 1, 1);
    cfg.blockDim = dim3(TPB, 1, 1);
    cfg.dynamicSmemBytes = TILE_BYTES;
    cudaLaunchAttribute attrs[1];
    attrs[0].id = cudaLaunchAttributeClusterDimension;
    attrs[0].val.clusterDim = {CLN, 1, 1};
    cfg.attrs = attrs;
    cfg.numAttrs = 1;

    cudaLaunchKernelEx(&cfg, attn_weights_kernel,
                       cls, qry, cw1, cb1, cw2, cb2, qw1, qb1, qw2, qb2);

    dim3 bgrid(2 * NSL, B, 1);
    apply_kernel<<<bgrid, BTPB>>>(cls, qry, oc, oq);
}